// round 13
// baseline (speedup 1.0000x reference)
#include <cuda_runtime.h>
#include <cstdint>

// ---------------------------------------------------------------------------
// Compile-time schedule: fold the 24 CNOT permutations (GF(2)-linear) into
// the gate shuffle masks (see R9).
// ---------------------------------------------------------------------------
struct PermSched { int sh[24]; int sel[24]; int fin[16]; };

constexpr PermSched make_sched() {
    PermSched P{};
    int F[4] = {1, 2, 4, 8};
    int G[4] = {1, 2, 4, 8};
    int g = 0;
    for (int l = 0; l < 6; ++l) {
        for (int w = 0; w < 4; ++w) {
            int b = 3 - w;
            P.sh[g] = G[b];
            int S = 0;
            for (int j = 0; j < 4; ++j) S |= ((F[j] >> b) & 1) << j;
            P.sel[g] = S;
            ++g;
        }
        int r = l % 3 + 1;
        for (int w = 0; w < 4; ++w) {
            int bc = 3 - w, bt = 3 - ((w + r) & 3);
            for (int b2 = 0; b2 < 4; ++b2)
                if ((F[b2] >> bc) & 1) F[b2] ^= (1 << bt);
            G[bc] ^= G[bt];
        }
    }
    for (int k = 0; k < 16; ++k) {
        int t = 0;
        for (int b = 0; b < 4; ++b) if ((k >> b) & 1) t ^= F[b];
        P.fin[k] = t;
    }
    return P;
}
__device__ constexpr PermSched PS = make_sched();

__device__ __forceinline__ float2 cmul(float2 a, float2 b) {
    return make_float2(a.x * b.x - a.y * b.y, a.x * b.y + a.y * b.x);
}

// tf32 truncation split: hi = top 19 bits (valid tf32), lo = exact remainder
__device__ __forceinline__ float tf32_hi(float x) {
    return __uint_as_float(__float_as_uint(x) & 0xFFFFE000u);
}

// m16n8k8 tf32 warp MMA, C += A*B  (fp32 accumulate)
__device__ __forceinline__ void mma_tf32(float* c,
                                         float a0, float a1, float a2, float a3,
                                         float b0, float b1) {
    asm volatile(
        "mma.sync.aligned.m16n8k8.row.col.f32.tf32.tf32.f32 "
        "{%0,%1,%2,%3}, {%4,%5,%6,%7}, {%8,%9}, {%0,%1,%2,%3};"
        : "+f"(c[0]), "+f"(c[1]), "+f"(c[2]), "+f"(c[3])
        : "r"(__float_as_uint(a0)), "r"(__float_as_uint(a1)),
          "r"(__float_as_uint(a2)), "r"(__float_as_uint(a3)),
          "r"(__float_as_uint(b0)), "r"(__float_as_uint(b1)));
}

#define WARPS 8
#define NGROUPS 8192   // 262144 / 32

// ---------------------------------------------------------------------------
// Fused tensor-core kernel, zero-staging A fragments, grid-stride balanced.
//   Prep per CTA: gate matrices -> shared; warps propagate 16 basis columns
//   (folded-perm shuffle butterflies) into sUc; B fragments (tf32 hi/lo).
//   Main grid-stride loop per warp over 32-element groups:
//     - A frags computed directly from x (s_j = h[t]*l[tid4]; no smem)
//     - next group's x loads issued BEFORE the mma block (prefetch)
//     - 48 mma in pass-outer order (8 independent C chains between reuses)
//     - |t|^2 + Z-sign butterfly epilogue (7 shfl / 4 elements)
// ---------------------------------------------------------------------------
__global__ __launch_bounds__(256, 2)
void qtc_kernel(const float4* __restrict__ x4, const float* __restrict__ wts,
                float4* __restrict__ out4) {
    __shared__ float2 sUc[256];    // sUc[j*16 + k] = U[k][j]
    __shared__ float2 sm[24][4];

    int tid  = threadIdx.x;
    int wid  = tid >> 5;
    int lane = tid & 31;
    int gid  = lane >> 2;   // mma "groupID"
    int tid4 = lane & 3;    // mma "threadID_in_group"

    // ---- gate matrices ----
    if (tid < 24) {
        float ph = wts[tid * 3 + 0];
        float th = wts[tid * 3 + 1];
        float om = wts[tid * 3 + 2];
        float st, ct; __sincosf(0.5f * th, &st, &ct);
        float sa, ca; __sincosf(0.5f * (ph + om), &sa, &ca);
        float sb, cb; __sincosf(0.5f * (ph - om), &sb, &cb);
        sm[tid][0] = make_float2( ca * ct, -sa * ct);
        sm[tid][1] = make_float2(-cb * st, -sb * st);
        sm[tid][2] = make_float2( cb * st, -sb * st);
        sm[tid][3] = make_float2( ca * ct,  sa * ct);
    }
    __syncthreads();

    // ---- U propagation: warps 0..7, two columns per warp ----
    {
        int k   = lane & 15;
        int col = wid + ((lane >> 4) << 3);
        float2 v = make_float2(k == col ? 1.0f : 0.0f, 0.0f);
#pragma unroll
        for (int g = 0; g < 24; ++g) {
            float2 m00 = sm[g][0], m01 = sm[g][1], m10 = sm[g][2], m11 = sm[g][3];
            float px = __shfl_xor_sync(0xffffffffu, v.x, PS.sh[g]);
            float py = __shfl_xor_sync(0xffffffffu, v.y, PS.sh[g]);
            float2 p = make_float2(px, py);
            bool hi = (__popc(k & PS.sel[g]) & 1) != 0;
            float2 cv = hi ? m11 : m00;
            float2 cp = hi ? m10 : m01;
            float2 a = cmul(cv, v), b = cmul(cp, p);
            v = make_float2(a.x + b.x, a.y + b.y);
        }
        sUc[col * 16 + PS.fin[k]] = v;
    }
    __syncthreads();

    // ---- B fragments: W[j][2k+c] = (c? Im : Re) U[k][j], tf32 hi/lo ----
    float bhi[2][4][2], blo[2][4][2];
#pragma unroll
    for (int kt = 0; kt < 2; ++kt)
#pragma unroll
    for (int nt = 0; nt < 4; ++nt) {
        int gn   = nt * 8 + gid;       // global output column
        int ko   = gn >> 1;            // k index
        int comp = gn & 1;             // 0=Re, 1=Im
#pragma unroll
        for (int r = 0; r < 2; ++r) {
            int j = tid4 + r * 4 + kt * 8;
            float2 u = sUc[j * 16 + ko];
            float w  = comp ? u.y : u.x;
            float wh = tf32_hi(w);
            bhi[kt][nt][r] = wh;
            blo[kt][nt][r] = w - wh;
        }
    }

    int W = gridDim.x * WARPS;                    // total warps
    int g = blockIdx.x * WARPS + wid;             // this warp's first group

    float4 xv[4];
    if (g < NGROUPS) {
#pragma unroll
        for (int m = 0; m < 4; ++m) xv[m] = x4[g * 32 + gid + 8 * m];
    }

#pragma unroll 1
    for (; g < NGROUPS; g += W) {
        int base = g * 32;

        // ---- A fragments from xv: Ahi/Alo[m][t] = split of
        //      s_{tid4+4t}(element gid+8m) = h[t]*l[tid4] ----
        float Ahi[4][4], Alo[4][4];
#pragma unroll
        for (int m = 0; m < 4; ++m) {
            float4 xa = xv[m];
            float c0, s0, c1, s1, c2, s2, c3, s3;
            __sincosf(0.5f * xa.x, &s0, &c0);
            __sincosf(0.5f * xa.y, &s1, &c1);
            __sincosf(0.5f * xa.z, &s2, &c2);
            __sincosf(0.5f * xa.w, &s3, &c3);
            float h0 = c0 * c1, h1 = c0 * s1, h2 = s0 * c1, h3 = s0 * s1;
            float lv = ((tid4 & 2) ? s2 : c2) * ((tid4 & 1) ? s3 : c3);
            float v0 = h0 * lv, v1 = h1 * lv, v2 = h2 * lv, v3 = h3 * lv;
            float w0 = tf32_hi(v0), w1 = tf32_hi(v1);
            float w2 = tf32_hi(v2), w3 = tf32_hi(v3);
            Ahi[m][0] = w0; Ahi[m][1] = w1; Ahi[m][2] = w2; Ahi[m][3] = w3;
            Alo[m][0] = v0 - w0; Alo[m][1] = v1 - w1;
            Alo[m][2] = v2 - w2; Alo[m][3] = v3 - w3;
        }

        // ---- prefetch next group's x (hidden behind the mma block) ----
        int gn2 = g + W;
        if (gn2 < NGROUPS) {
#pragma unroll
            for (int m = 0; m < 4; ++m) xv[m] = x4[gn2 * 32 + gid + 8 * m];
        }

        // ---- GEMM: 48 mma, PASS-OUTER order (8 independent C chains) ----
        float C[2][4][4];
#pragma unroll
        for (int mt = 0; mt < 2; ++mt)
#pragma unroll
            for (int nt = 0; nt < 4; ++nt)
#pragma unroll
                for (int r = 0; r < 4; ++r) C[mt][nt][r] = 0.0f;

#pragma unroll
        for (int pass = 0; pass < 3; ++pass) {
#pragma unroll
            for (int mt = 0; mt < 2; ++mt) {
#pragma unroll
                for (int kt = 0; kt < 2; ++kt) {
                    // A regs for this (mt, kt): rows m = 2mt, 2mt+1; t = 2kt, 2kt+1
                    const float (*Asel)[4] = (pass == 2) ? Alo : Ahi;
                    float a0 = Asel[2 * mt][2 * kt];
                    float a1 = Asel[2 * mt + 1][2 * kt];
                    float a2 = Asel[2 * mt][2 * kt + 1];
                    float a3 = Asel[2 * mt + 1][2 * kt + 1];
                    const float (*Bsel)[4][2] = (pass == 1) ? blo : bhi;
#pragma unroll
                    for (int nt = 0; nt < 4; ++nt)
                        mma_tf32(C[mt][nt], a0, a1, a2, a3,
                                 Bsel[kt][nt][0], Bsel[kt][nt][1]);
                }
            }
        }

        // ---- epilogue: |t|^2 + Z-sign butterfly (7 shfl per ei) ----
        float o[4][4];
#pragma unroll
        for (int ei = 0; ei < 4; ++ei) {
            int mt = ei >> 1, hf = ei & 1;
            float p[4];
#pragma unroll
            for (int nt = 0; nt < 4; ++nt) {
                float re = C[mt][nt][hf * 2 + 0];
                float im = C[mt][nt][hf * 2 + 1];
                p[nt] = re * re + im * im;
            }
            float s01 = p[0] + p[1], s23 = p[2] + p[3];
            float T2  = s01 + s23;
            float q0p = s01 - s23;                       // sign bit3 (nt>>1)
            float q1p = (p[0] - p[1]) + (p[2] - p[3]);   // sign bit2 (nt&1)
            q0p += __shfl_xor_sync(0xffffffffu, q0p, 1);
            q0p += __shfl_xor_sync(0xffffffffu, q0p, 2);
            q1p += __shfl_xor_sync(0xffffffffu, q1p, 1);
            q1p += __shfl_xor_sync(0xffffffffu, q1p, 2);
            float x1 = __shfl_xor_sync(0xffffffffu, T2, 1);
            float sfull = T2 + x1;
            float d = (tid4 & 1) ? (x1 - T2) : (T2 - x1);
            float m2 = __shfl_xor_sync(0xffffffffu, sfull, 2);
            float v2 = (tid4 & 2) ? (m2 - sfull) : (sfull - m2);
            float d2 = __shfl_xor_sync(0xffffffffu, d, 2);
            float v3 = d + d2;
            o[ei][0] = q0p; o[ei][1] = q1p; o[ei][2] = v2; o[ei][3] = v3;
        }

        float4 ov = make_float4(o[0][0], o[0][1], o[0][2], o[0][3]);
        if (tid4 == 1) ov = make_float4(o[1][0], o[1][1], o[1][2], o[1][3]);
        if (tid4 == 2) ov = make_float4(o[2][0], o[2][1], o[2][2], o[2][3]);
        if (tid4 == 3) ov = make_float4(o[3][0], o[3][1], o[3][2], o[3][3]);
        out4[base + gid + 8 * tid4] = ov;
    }
}

extern "C" void kernel_launch(void* const* d_in, const int* in_sizes, int n_in,
                              void* d_out, int out_size) {
    const float* x   = (const float*)d_in[0];
    const float* wts = (const float*)d_in[1];
    if (n_in >= 2 && in_sizes[0] == 72 && in_sizes[1] != 72) {
        wts = (const float*)d_in[0];
        x   = (const float*)d_in[1];
    }
    // grid = 2 CTAs per SM (148 SMs on sm_100a) for exact wave balance;
    // grid-stride loop covers all NGROUPS groups regardless.
    int grid = 296;
    qtc_kernel<<<grid, 256>>>((const float4*)x, wts, (float4*)d_out);
}